// round 13
// baseline (speedup 1.0000x reference)
#include <cuda_runtime.h>
#include <cstdint>

#define B 8
#define T 4096
#define D 1024
#define S 64
#define BOND 32
#define NQ 8
#define QDIM 256
#define NCH 128        // chunks per batch (32 rows each)
#define NMID 64        // k_mid blocks (co-resident, gbar-safe)

// ------- device scratch (no allocations allowed) -------
__device__ float g_part[B * NCH * D];    // per-chunk column sums (4 MB)
__device__ float g_m0[B * 32];           // padded per batch
__device__ float g_m1[B * 32];
__device__ float g_overlaps[B * S];
__device__ float g_feats[S * NQ];
__device__ float g_fold[NQ * D];         // folded Wd
__device__ float g_bias[B * D];          // final per-batch bias rows
__device__ int   g_bar_count;            // zero-init
__device__ int   g_bar_gen;

// ---------------- software grid barrier (NMID blocks, all co-resident) ----------------
__device__ __forceinline__ void gbar() {
    __threadfence();
    __syncthreads();
    if (threadIdx.x == 0) {
        int gen = *(volatile int*)&g_bar_gen;
        if (atomicAdd(&g_bar_count, 1) == NMID - 1) {
            *(volatile int*)&g_bar_count = 0;
            __threadfence();
            *(volatile int*)&g_bar_gen = gen + 1;
        } else {
            while (*(volatile int*)&g_bar_gen == gen) __nanosleep(64);
        }
    }
    __syncthreads();
}

// ============ Kernel 1: per-chunk column sums (32 rows/block, no smem reduce) ============
__global__ void k_partsum(const float* __restrict__ x) {
    const int c = blockIdx.x;      // chunk
    const int b = blockIdx.y;      // batch
    const int tid = threadIdx.x;   // float4 column
    const float4* xp = reinterpret_cast<const float4*>(x) +
                       ((size_t)b * T + (size_t)c * 32) * 256 + tid;
    float4 acc = make_float4(0.f, 0.f, 0.f, 0.f);
#pragma unroll 8
    for (int r = 0; r < 32; ++r) {
        float4 v = xp[(size_t)r * 256];
        acc.x += v.x; acc.y += v.y; acc.z += v.z; acc.w += v.w;
    }
    reinterpret_cast<float4*>(g_part)[((size_t)b * NCH + c) * 256 + tid] = acc;
}

// ============ Kernel 2: middle work — query | fold, slots, attention+bias ============
__global__ void __launch_bounds__(256, 1)
k_mid(const float* __restrict__ Wq,
      const float* __restrict__ bq,
      const float* __restrict__ Wd,
      const float* __restrict__ bd,
      const float* __restrict__ cf,
      const float* __restrict__ cm,
      const float* __restrict__ cl) {
    __shared__ float smem[12288];   // 48 KB
    const int blk = blockIdx.x;
    const int tid = threadIdx.x;

    // ---------------- Phase A: query (blocks 0..7) | fold Wd (blocks 8..39) ----------------
    if (blk < B) {
        float* xs = smem;           // 1024
        float* qa = smem + 1024;    // 256
        float* red = smem + 1280;   // 8
        const int b = blk;
        // gather partials: thread t owns d = t, t+256, t+512, t+768
#pragma unroll
        for (int h = 0; h < 4; ++h) {
            const int d = tid + h * 256;
            float acc = 0.f;
            const float* p = g_part + (size_t)b * NCH * D + d;
#pragma unroll 8
            for (int c = 0; c < NCH; ++c) acc += p[(size_t)c * D];
            xs[d] = acc * (1.0f / (float)T);
        }
        __syncthreads();

        // GEMV: j = tid (exactly 256 threads = QDIM, no guards anywhere)
        const int j = tid;
        float a0 = 0.f, a1 = 0.f, a2 = 0.f, a3 = 0.f;
#pragma unroll 4
        for (int k = 0; k < D; k += 4) {
            a0 = fmaf(xs[k + 0], Wq[(size_t)(k + 0) * QDIM + j], a0);
            a1 = fmaf(xs[k + 1], Wq[(size_t)(k + 1) * QDIM + j], a1);
            a2 = fmaf(xs[k + 2], Wq[(size_t)(k + 2) * QDIM + j], a2);
            a3 = fmaf(xs[k + 3], Wq[(size_t)(k + 3) * QDIM + j], a3);
        }
        float logit = (a0 + a1) + (a2 + a3) + bq[j];

        // softmax over 256
        float m = logit;
#pragma unroll
        for (int o = 16; o; o >>= 1) m = fmaxf(m, __shfl_xor_sync(0xffffffffu, m, o));
        if ((tid & 31) == 0) red[tid >> 5] = m;
        __syncthreads();
        float bm = red[0];
#pragma unroll
        for (int i = 1; i < 8; ++i) bm = fmaxf(bm, red[i]);
        float e = __expf(logit - bm);
        float ssum = e;
#pragma unroll
        for (int o = 16; o; o >>= 1) ssum += __shfl_xor_sync(0xffffffffu, ssum, o);
        __syncthreads();
        if ((tid & 31) == 0) red[tid >> 5] = ssum;
        __syncthreads();
        float tot = 0.f;
#pragma unroll
        for (int i = 0; i < 8; ++i) tot += red[i];
        qa[j] = e / tot;
        __syncthreads();

        if (tid < 16) {   // amplitude means, JAX OOB-clamp to index 255
            const int q = tid & 7;
            const bool one = tid >= 8;
            const int s = 1 << (7 - q);
            const int cin = min(s, 128 / s);
            float a = 0.f;
            const int off = one ? s : 0;
            for (int i = 0; i < cin; ++i) a += qa[i * 2 * s + off];
            a += (float)(s - cin) * qa[QDIM - 1];
            float* dst = one ? g_m1 : g_m0;
            dst[b * 32 + q] = a / (float)s;
        }
    } else if (blk < 40) {
        // fold[q][d] = sum_i Wd[i*8+q][d]; block p covers d in [p*32, p*32+32)
        const int p = blk - 8;
        const int d = p * 32 + (tid >> 3);
        const int q = tid & 7;
        float acc = 0.f;
#pragma unroll 8
        for (int i = 0; i < 32; ++i)
            acc += Wd[(size_t)(i * 8 + q) * D + d];
        g_fold[q * D + d] = acc;
    }
    gbar();

    // ---------------- Phase B: slots (all 64 blocks; slot = blk) ----------------
    {
        const int s = blk;
        {   // stage cm slice (48 KB) coalesced
            const float4* src = reinterpret_cast<const float4*>(cm + (size_t)s * 12288);
            float4* dst = reinterpret_cast<float4*>(smem);
#pragma unroll
            for (int i = 0; i < 12; ++i)
                dst[i * 256 + tid] = src[i * 256 + tid];
        }
        __syncthreads();

        const int w = tid >> 5;
        const int lane = tid & 31;
        // feats
        float fsum, inv_cnt;
        if (w == 0) {
            fsum = cf[s * 64 + lane] + cf[s * 64 + 32 + lane];
            inv_cnt = 1.0f / 64.0f;
        } else if (w == 7) {
            fsum = cl[s * 64 + lane] + cl[s * 64 + 32 + lane];
            inv_cnt = 1.0f / 64.0f;
        } else {
            const float* base = smem + (w - 1) * 2048;
            fsum = 0.f;
#pragma unroll
            for (int i = 0; i < 64; ++i) fsum += base[i * 32 + lane];
            inv_cnt = 1.0f / 2048.0f;
        }
#pragma unroll
        for (int o = 16; o; o >>= 1) fsum += __shfl_xor_sync(0xffffffffu, fsum, o);
        if (lane == 0) g_feats[s * NQ + w] = fsum * inv_cnt;

        // overlap for batch b = w (warp per batch)
        const int b = w;
        float M0[NQ], M1[NQ];
#pragma unroll
        for (int q = 0; q < NQ; ++q) {
            M0[q] = __ldcg(&g_m0[b * 32 + q]);
            M1[q] = __ldcg(&g_m1[b * 32 + q]);
        }
        float v = M0[0] * cf[s * 64 + lane] + M1[0] * cf[s * 64 + 32 + lane];
#pragma unroll
        for (int q = 1; q <= NQ - 2; ++q) {
            const float* base = smem + (q - 1) * 2048;
            float nv = 0.f;
#pragma unroll 8
            for (int l = 0; l < BOND; ++l) {
                float vl = __shfl_sync(0xffffffffu, v, l);
                float c0 = base[l * 64 + lane];
                float c1 = base[l * 64 + 32 + lane];
                nv = fmaf(vl, fmaf(M0[q], c0, M1[q] * c1), nv);
            }
            v = nv;
        }
        float wl = M0[NQ - 1] * cl[(s * BOND + lane) * 2] +
                   M1[NQ - 1] * cl[(s * BOND + lane) * 2 + 1];
        float ov = v * wl;
#pragma unroll
        for (int o = 16; o; o >>= 1) ov += __shfl_xor_sync(0xffffffffu, ov, o);
        if (lane == 0) g_overlaps[b * S + s] = ov;
    }
    gbar();

    // ---------------- Phase C: blocks 0..7 — attention + bias row ----------------
    if (blk < B) {
        const int b = blk;
        float* s_gg = smem;   // 8

        if (tid < 32) {
            const int lane = tid;
            float a0 = __ldcg(&g_overlaps[b * S + lane]);
            float a1 = __ldcg(&g_overlaps[b * S + 32 + lane]);
            float m = fmaxf(a0, a1);
#pragma unroll
            for (int o = 16; o; o >>= 1) m = fmaxf(m, __shfl_xor_sync(0xffffffffu, m, o));
            float e0 = __expf(a0 - m);
            float e1 = __expf(a1 - m);
            float ssum = e0 + e1;
#pragma unroll
            for (int o = 16; o; o >>= 1) ssum += __shfl_xor_sync(0xffffffffu, ssum, o);
            const float inv = 1.0f / ssum;
            const float at0 = e0 * inv;
            const float at1 = e1 * inv;
#pragma unroll
            for (int q = 0; q < NQ; ++q) {
                float p = at0 * __ldcg(&g_feats[lane * NQ + q]) +
                          at1 * __ldcg(&g_feats[(32 + lane) * NQ + q]);
#pragma unroll
                for (int o = 16; o; o >>= 1) p += __shfl_xor_sync(0xffffffffu, p, o);
                if (lane == 0) s_gg[q] = p;
            }
        }
        __syncthreads();

#pragma unroll
        for (int h = 0; h < 4; ++h) {
            const int d = tid + h * 256;
            float acc = bd[d];
#pragma unroll
            for (int q = 0; q < NQ; ++q)
                acc = fmaf(s_gg[q], __ldcg(&g_fold[q * D + d]), acc);
            g_bias[b * D + d] = acc;
        }
    }
}

// ============ Kernel 3: out = x + bias (proven config: 8192 x 256) ============
__global__ void k_add(const float* __restrict__ x, float* __restrict__ out) {
    const int blk = blockIdx.x;
    const int b = blk >> 10;               // 1024 blocks per batch
    const size_t row0 = (size_t)blk * 4;
    const int tid = threadIdx.x;
    const float4 bias = reinterpret_cast<const float4*>(g_bias)[b * (D / 4) + tid];
    const float4* xp = reinterpret_cast<const float4*>(x) + row0 * (D / 4);
    float4* op = reinterpret_cast<float4*>(out) + row0 * (D / 4);
#pragma unroll
    for (int r = 0; r < 4; ++r) {
        float4 v = xp[r * (D / 4) + tid];
        v.x += bias.x; v.y += bias.y; v.z += bias.z; v.w += bias.w;
        op[r * (D / 4) + tid] = v;
    }
}

extern "C" void kernel_launch(void* const* d_in, const int* in_sizes, int n_in,
                              void* d_out, int out_size) {
    const float* x  = (const float*)d_in[0];
    const float* Wq = (const float*)d_in[1];
    const float* bq = (const float*)d_in[2];
    const float* Wd = (const float*)d_in[3];
    const float* bd = (const float*)d_in[4];
    const float* cf = (const float*)d_in[5];
    const float* cm = (const float*)d_in[6];
    const float* cl = (const float*)d_in[7];
    float* out = (float*)d_out;

    k_partsum<<<dim3(NCH, B), 256>>>(x);
    k_mid<<<NMID, 256>>>(Wq, bq, Wd, bd, cf, cm, cl);
    k_add<<<(B * T) / 4, 256>>>(x, out);
}

// round 14
// speedup vs baseline: 1.3783x; 1.3783x over previous
#include <cuda_runtime.h>
#include <cstdint>

#define B 8
#define T 4096
#define D 1024
#define S 64
#define BOND 32
#define NQ 8
#define QDIM 256
#define NCH 64         // chunks per batch (64 rows each)
#define NMID 148       // k_mid blocks (one per SM, co-resident, gbar-safe)
#define NT 1024

// ------- device scratch (no allocations allowed) -------
__device__ float g_part[B * NCH * D];    // per-chunk column sums (2 MB)
__device__ float g_m0[B * 32];           // padded per batch
__device__ float g_m1[B * 32];
__device__ float g_overlaps[B * S];
__device__ float g_feats[S * NQ];
__device__ float g_fold[NQ * D];         // folded Wd
__device__ float g_bias[B * D];          // final per-batch bias rows
__device__ int   g_bar_count;            // zero-init
__device__ int   g_bar_gen;

// ---------------- software grid barrier (NMID blocks, all co-resident) ----------------
__device__ __forceinline__ void gbar() {
    __threadfence();
    __syncthreads();
    if (threadIdx.x == 0) {
        int gen = *(volatile int*)&g_bar_gen;
        if (atomicAdd(&g_bar_count, 1) == NMID - 1) {
            *(volatile int*)&g_bar_count = 0;
            __threadfence();
            *(volatile int*)&g_bar_gen = gen + 1;
        } else {
            while (*(volatile int*)&g_bar_gen == gen) __nanosleep(64);
        }
    }
    __syncthreads();
}

// ============ Kernel 1: per-chunk column sums (64 rows/block, proven recipe) ============
__global__ void k_partsum(const float* __restrict__ x) {
    const int c = blockIdx.x;      // chunk
    const int b = blockIdx.y;      // batch
    const int tid = threadIdx.x;   // float4 column
    const float4* xp = reinterpret_cast<const float4*>(x) +
                       ((size_t)b * T + (size_t)c * 64) * 256 + tid;
    float4 acc = make_float4(0.f, 0.f, 0.f, 0.f);
#pragma unroll 8
    for (int r = 0; r < 64; ++r) {
        float4 v = xp[(size_t)r * 256];
        acc.x += v.x; acc.y += v.y; acc.z += v.z; acc.w += v.w;
    }
    reinterpret_cast<float4*>(g_part)[((size_t)b * NCH + c) * 256 + tid] = acc;
}

// ============ Kernel 2: middle work, 148 x 1024 (R12 structure) ============
__global__ void __launch_bounds__(NT, 1)
k_mid(const float* __restrict__ Wq,
      const float* __restrict__ bq,
      const float* __restrict__ Wd,
      const float* __restrict__ bd,
      const float* __restrict__ cf,
      const float* __restrict__ cm,
      const float* __restrict__ cl) {
    __shared__ float smem[12288];   // 48 KB
    const int blk = blockIdx.x;
    const int tid = threadIdx.x;

    // === Phase A: query (0..7) | fold Wd (8..39) | preload cm (84..147) ===
    if (blk < B) {
        float* xs = smem;           // 1024
        float* pr = smem + 1024;    // 1024 (4 x 256)
        float* qa = smem + 2048;    // 256
        float* red = smem + 2304;   // 8
        const int b = blk;
        {   // gather: thread tid owns column d = tid (coalesced, L2-hot)
            float acc = 0.f;
            const float* p = g_part + (size_t)b * NCH * D + tid;
#pragma unroll 8
            for (int c = 0; c < NCH; ++c) acc += p[(size_t)c * D];
            xs[tid] = acc * (1.0f / (float)T);
        }
        __syncthreads();

        const int j = tid & 255;
        const int kc = tid >> 8;
        const int k0 = kc * 256;
        {
            float a = 0.f;
#pragma unroll 8
            for (int k = 0; k < 256; ++k)
                a = fmaf(xs[k0 + k], Wq[(size_t)(k0 + k) * QDIM + j], a);
            pr[kc * 256 + j] = a;
        }
        __syncthreads();

        float logit = 0.f;
        if (tid < QDIM)
            logit = (pr[j] + pr[256 + j]) + (pr[512 + j] + pr[768 + j]) + bq[j];

        // softmax over 256 — barriers in uniform control flow
        float m = logit;
#pragma unroll
        for (int o = 16; o; o >>= 1) m = fmaxf(m, __shfl_xor_sync(0xffffffffu, m, o));
        if (tid < QDIM && (tid & 31) == 0) red[tid >> 5] = m;
        __syncthreads();
        float bm = red[0];
#pragma unroll
        for (int i = 1; i < 8; ++i) bm = fmaxf(bm, red[i]);
        float e = (tid < QDIM) ? __expf(logit - bm) : 0.f;
        float ssum = e;
#pragma unroll
        for (int o = 16; o; o >>= 1) ssum += __shfl_xor_sync(0xffffffffu, ssum, o);
        __syncthreads();
        if (tid < QDIM && (tid & 31) == 0) red[tid >> 5] = ssum;
        __syncthreads();
        float tot = 0.f;
#pragma unroll
        for (int i = 0; i < 8; ++i) tot += red[i];
        if (tid < QDIM) qa[j] = e / tot;
        __syncthreads();

        if (tid < 16) {   // amplitude means, JAX OOB-clamp to index 255
            const int q = tid & 7;
            const bool one = tid >= 8;
            const int s = 1 << (7 - q);
            const int cin = min(s, 128 / s);
            float a = 0.f;
            const int off = one ? s : 0;
            for (int i = 0; i < cin; ++i) a += qa[i * 2 * s + off];
            a += (float)(s - cin) * qa[QDIM - 1];
            float* dst = one ? g_m1 : g_m0;
            dst[b * 32 + q] = a / (float)s;
        }
    } else if (blk < 40) {
        // fold[q][d] = sum_i Wd[i*8+q][d]
        if (tid < 256) {
            const int p = blk - 8;
            const int d = p * 32 + (tid >> 3);
            const int q = tid & 7;
            float acc = 0.f;
#pragma unroll 8
            for (int i = 0; i < 32; ++i)
                acc += Wd[(size_t)(i * 8 + q) * D + d];
            g_fold[q * D + d] = acc;
        }
    } else if (blk >= 84) {
        // coalesced preload of this slot's cm slice into smem
        const int s = blk - 84;
        const float4* src = reinterpret_cast<const float4*>(cm + (size_t)s * 12288);
        float4* dst = reinterpret_cast<float4*>(smem);
#pragma unroll
        for (int i = 0; i < 3; ++i)
            dst[i * 1024 + tid] = src[i * 1024 + tid];
    }
    gbar();

    // ============ Phase B: slots (blocks 84..147; cm already in smem) ============
    if (blk >= 84) {
        const int s = blk - 84;
        if (tid < 256) {
            const int w = tid >> 5;
            const int lane = tid & 31;
            float fsum, inv_cnt;
            if (w == 0) {
                fsum = cf[s * 64 + lane] + cf[s * 64 + 32 + lane];
                inv_cnt = 1.0f / 64.0f;
            } else if (w == 7) {
                fsum = cl[s * 64 + lane] + cl[s * 64 + 32 + lane];
                inv_cnt = 1.0f / 64.0f;
            } else {
                const float* base = smem + (w - 1) * 2048;
                fsum = 0.f;
#pragma unroll
                for (int i = 0; i < 64; ++i) fsum += base[i * 32 + lane];
                inv_cnt = 1.0f / 2048.0f;
            }
#pragma unroll
            for (int o = 16; o; o >>= 1) fsum += __shfl_xor_sync(0xffffffffu, fsum, o);
            if (lane == 0) g_feats[s * NQ + w] = fsum * inv_cnt;

            const int b = w;   // batch = warp
            float M0[NQ], M1[NQ];
#pragma unroll
            for (int q = 0; q < NQ; ++q) {
                M0[q] = __ldcg(&g_m0[b * 32 + q]);
                M1[q] = __ldcg(&g_m1[b * 32 + q]);
            }
            float v = M0[0] * cf[s * 64 + lane] + M1[0] * cf[s * 64 + 32 + lane];
#pragma unroll
            for (int q = 1; q <= NQ - 2; ++q) {
                const float* base = smem + (q - 1) * 2048;
                float nv = 0.f;
#pragma unroll 8
                for (int l = 0; l < BOND; ++l) {
                    float vl = __shfl_sync(0xffffffffu, v, l);
                    float c0 = base[l * 64 + lane];
                    float c1 = base[l * 64 + 32 + lane];
                    nv = fmaf(vl, fmaf(M0[q], c0, M1[q] * c1), nv);
                }
                v = nv;
            }
            float wl = M0[NQ - 1] * cl[(s * BOND + lane) * 2] +
                       M1[NQ - 1] * cl[(s * BOND + lane) * 2 + 1];
            float ov = v * wl;
#pragma unroll
            for (int o = 16; o; o >>= 1) ov += __shfl_xor_sync(0xffffffffu, ov, o);
            if (lane == 0) g_overlaps[b * S + s] = ov;
        }
    }
    gbar();

    // ===== Phase C: blocks 0..7 — attention + gg for batch b, write bias row =====
    if (blk < B) {
        const int b = blk;
        float* s_gg = smem;   // 8

        if (tid < 32) {
            const int lane = tid;
            float a0 = __ldcg(&g_overlaps[b * S + lane]);
            float a1 = __ldcg(&g_overlaps[b * S + 32 + lane]);
            float m = fmaxf(a0, a1);
#pragma unroll
            for (int o = 16; o; o >>= 1) m = fmaxf(m, __shfl_xor_sync(0xffffffffu, m, o));
            float e0 = __expf(a0 - m);
            float e1 = __expf(a1 - m);
            float ssum = e0 + e1;
#pragma unroll
            for (int o = 16; o; o >>= 1) ssum += __shfl_xor_sync(0xffffffffu, ssum, o);
            const float inv = 1.0f / ssum;
            const float at0 = e0 * inv;
            const float at1 = e1 * inv;
#pragma unroll
            for (int q = 0; q < NQ; ++q) {
                float p = at0 * __ldcg(&g_feats[lane * NQ + q]) +
                          at1 * __ldcg(&g_feats[(32 + lane) * NQ + q]);
#pragma unroll
                for (int o = 16; o; o >>= 1) p += __shfl_xor_sync(0xffffffffu, p, o);
                if (lane == 0) s_gg[q] = p;
            }
        }
        __syncthreads();

        float acc = bd[tid];
#pragma unroll
        for (int q = 0; q < NQ; ++q)
            acc = fmaf(s_gg[q], __ldcg(&g_fold[q * D + tid]), acc);
        g_bias[b * D + tid] = acc;
    }
}

// ============ Kernel 3: out = x + bias (proven config: 8192 x 256) ============
__global__ void k_add(const float* __restrict__ x, float* __restrict__ out) {
    const int blk = blockIdx.x;
    const int b = blk >> 10;               // 1024 blocks per batch
    const size_t row0 = (size_t)blk * 4;
    const int tid = threadIdx.x;
    const float4 bias = reinterpret_cast<const float4*>(g_bias)[b * (D / 4) + tid];
    const float4* xp = reinterpret_cast<const float4*>(x) + row0 * (D / 4);
    float4* op = reinterpret_cast<float4*>(out) + row0 * (D / 4);
#pragma unroll
    for (int r = 0; r < 4; ++r) {
        float4 v = xp[r * (D / 4) + tid];
        v.x += bias.x; v.y += bias.y; v.z += bias.z; v.w += bias.w;
        op[r * (D / 4) + tid] = v;
    }
}

extern "C" void kernel_launch(void* const* d_in, const int* in_sizes, int n_in,
                              void* d_out, int out_size) {
    const float* x  = (const float*)d_in[0];
    const float* Wq = (const float*)d_in[1];
    const float* bq = (const float*)d_in[2];
    const float* Wd = (const float*)d_in[3];
    const float* bd = (const float*)d_in[4];
    const float* cf = (const float*)d_in[5];
    const float* cm = (const float*)d_in[6];
    const float* cl = (const float*)d_in[7];
    float* out = (float*)d_out;

    k_partsum<<<dim3(NCH, B), 256>>>(x);
    k_mid<<<NMID, NT>>>(Wq, bq, Wd, bd, cf, cm, cl);
    k_add<<<(B * T) / 4, 256>>>(x, out);
}

// round 15
// speedup vs baseline: 1.6360x; 1.1869x over previous
#include <cuda_runtime.h>
#include <cstdint>

#define B 8
#define T 4096
#define D 1024
#define S 64
#define BOND 32
#define NQ 8
#define QDIM 256
#define NCH 64         // chunks per batch (64 rows each)
#define NMID 80        // k_mid blocks (co-resident, gbar-safe)
#define NT 1024

// ------- device scratch (no allocations allowed) -------
__device__ float g_part[B * NCH * D];    // per-chunk column sums (2 MB)
__device__ float g_lp[64 * B * QDIM];    // per-kslice logit partials (512 KB)
__device__ float g_m0[B * 32];           // padded per batch
__device__ float g_m1[B * 32];
__device__ float g_overlaps[B * S];
__device__ float g_feats[S * NQ];
__device__ float g_fold[NQ * D];         // folded Wd
__device__ float g_bias[B * D];          // final per-batch bias rows
__device__ int   g_bar_count;            // zero-init
__device__ int   g_bar_gen;

// ---------------- software grid barrier (NMID blocks, all co-resident) ----------------
__device__ __forceinline__ void gbar() {
    __threadfence();
    __syncthreads();
    if (threadIdx.x == 0) {
        int gen = *(volatile int*)&g_bar_gen;
        if (atomicAdd(&g_bar_count, 1) == NMID - 1) {
            *(volatile int*)&g_bar_count = 0;
            __threadfence();
            *(volatile int*)&g_bar_gen = gen + 1;
        } else {
            while (*(volatile int*)&g_bar_gen == gen) __nanosleep(64);
        }
    }
    __syncthreads();
}

// ============ Kernel 1: per-chunk column sums (proven recipe) ============
__global__ void k_partsum(const float* __restrict__ x) {
    const int c = blockIdx.x;
    const int b = blockIdx.y;
    const int tid = threadIdx.x;
    const float4* xp = reinterpret_cast<const float4*>(x) +
                       ((size_t)b * T + (size_t)c * 64) * 256 + tid;
    float4 acc = make_float4(0.f, 0.f, 0.f, 0.f);
#pragma unroll 8
    for (int r = 0; r < 64; ++r) {
        float4 v = xp[(size_t)r * 256];
        acc.x += v.x; acc.y += v.y; acc.z += v.z; acc.w += v.w;
    }
    reinterpret_cast<float4*>(g_part)[((size_t)b * NCH + c) * 256 + tid] = acc;
}

// ============ Kernel 2: middle work, 80 x 1024, 3 gbars ============
__global__ void __launch_bounds__(NT, 1)
k_mid(const float* __restrict__ Wq,
      const float* __restrict__ bq,
      const float* __restrict__ Wd,
      const float* __restrict__ bd,
      const float* __restrict__ cf,
      const float* __restrict__ cm,
      const float* __restrict__ cl) {
    __shared__ float smem[12288];   // 48 KB
    const int blk = blockIdx.x;
    const int tid = threadIdx.x;

    // ===== P1: GEMV partials for ALL batches (blocks 0..63) | fold Wd (64..79) =====
    if (blk < 64) {
        float* pr = smem;            // 4 x 8 x 256 = 8192 floats (32 KB)
        float* xs_s = smem + 8192;   // 8 x 16 = 128 floats
        const int k0 = blk * 16;

        // self-gather xs slice: pair = (b, k'), 8 sub-threads each sum 8 c's
        {
            const int pair = tid >> 3;         // 0..127
            const int sub = tid & 7;
            const int b = pair >> 4;
            const int kk = pair & 15;
            float acc = 0.f;
#pragma unroll
            for (int m = 0; m < 8; ++m)
                acc += g_part[((size_t)b * NCH + (sub + 8 * m)) * D + k0 + kk];
#pragma unroll
            for (int o = 4; o; o >>= 1) acc += __shfl_xor_sync(0xffffffffu, acc, o);
            if (sub == 0) xs_s[b * 16 + kk] = acc * (1.0f / (float)T);
        }
        __syncthreads();

        // partial GEMV: thread (j, kc) covers 4 k's for all 8 batches
        const int j = tid & 255;
        const int kc = tid >> 8;
        {
            float acc[B];
#pragma unroll
            for (int b = 0; b < B; ++b) acc[b] = 0.f;
#pragma unroll
            for (int i = 0; i < 4; ++i) {
                const int kk = kc * 4 + i;
                const float wq = Wq[(size_t)(k0 + kk) * QDIM + j];
#pragma unroll
                for (int b = 0; b < B; ++b)
                    acc[b] = fmaf(xs_s[b * 16 + kk], wq, acc[b]);
            }
#pragma unroll
            for (int b = 0; b < B; ++b)
                pr[(kc * 8 + b) * 256 + j] = acc[b];
        }
        __syncthreads();

        // reduce over kc, store g_lp[blk][b][j]
#pragma unroll
        for (int h = 0; h < 2; ++h) {
            const int idx = tid + h * 1024;    // (b, j)
            const int b = idx >> 8;
            const int jj = idx & 255;
            float v = pr[(0 * 8 + b) * 256 + jj] + pr[(1 * 8 + b) * 256 + jj] +
                      pr[(2 * 8 + b) * 256 + jj] + pr[(3 * 8 + b) * 256 + jj];
            g_lp[((size_t)blk * B + b) * QDIM + jj] = v;
        }
    } else {
        // fold[q][d] = sum_i Wd[i*8+q][d]; block covers 64 d's
        if (tid < 512) {
            const int d = (blk - 64) * 64 + (tid >> 3);
            const int q = tid & 7;
            float acc = 0.f;
#pragma unroll 8
            for (int i = 0; i < 32; ++i)
                acc += Wd[(size_t)(i * 8 + q) * D + d];
            g_fold[q * D + d] = acc;
        }
    }
    gbar();

    // ===== P2: query finish (blocks 0..7) | cm preload + feats (blocks 16..79) =====
    if (blk < B) {
        float* pr2 = smem;           // 4 x 256
        float* qa = smem + 1024;     // 256
        float* red = smem + 1280;    // 8
        const int b = blk;
        const int j = tid & 255;
        const int pc = tid >> 8;
        {
            float acc = 0.f;
#pragma unroll
            for (int i = 0; i < 16; ++i) {
                const int p = pc * 16 + i;
                acc += g_lp[((size_t)p * B + b) * QDIM + j];
            }
            pr2[pc * 256 + j] = acc;
        }
        __syncthreads();

        float logit = 0.f;
        if (tid < QDIM)
            logit = (pr2[j] + pr2[256 + j]) + (pr2[512 + j] + pr2[768 + j]) + bq[j];

        // softmax over 256 — barriers uniform
        float m = logit;
#pragma unroll
        for (int o = 16; o; o >>= 1) m = fmaxf(m, __shfl_xor_sync(0xffffffffu, m, o));
        if (tid < QDIM && (tid & 31) == 0) red[tid >> 5] = m;
        __syncthreads();
        float bm = red[0];
#pragma unroll
        for (int i = 1; i < 8; ++i) bm = fmaxf(bm, red[i]);
        float e = (tid < QDIM) ? __expf(logit - bm) : 0.f;
        float ssum = e;
#pragma unroll
        for (int o = 16; o; o >>= 1) ssum += __shfl_xor_sync(0xffffffffu, ssum, o);
        __syncthreads();
        if (tid < QDIM && (tid & 31) == 0) red[tid >> 5] = ssum;
        __syncthreads();
        float tot = 0.f;
#pragma unroll
        for (int i = 0; i < 8; ++i) tot += red[i];
        if (tid < QDIM) qa[j] = e / tot;
        __syncthreads();

        if (tid < 16) {   // amplitude means, JAX OOB-clamp to index 255
            const int q = tid & 7;
            const bool one = tid >= 8;
            const int s = 1 << (7 - q);
            const int cin = min(s, 128 / s);
            float a = 0.f;
            const int off = one ? s : 0;
            for (int i = 0; i < cin; ++i) a += qa[i * 2 * s + off];
            a += (float)(s - cin) * qa[QDIM - 1];
            float* dst = one ? g_m1 : g_m0;
            dst[b * 32 + q] = a / (float)s;
        }
    } else if (blk >= 16) {
        // preload this slot's cm slice into smem + compute feats (query-independent)
        const int s = blk - 16;
        {
            const float4* src = reinterpret_cast<const float4*>(cm + (size_t)s * 12288);
            float4* dst = reinterpret_cast<float4*>(smem);
#pragma unroll
            for (int i = 0; i < 3; ++i)
                dst[i * 1024 + tid] = src[i * 1024 + tid];
        }
        __syncthreads();

        if (tid < 256) {
            const int w = tid >> 5;
            const int lane = tid & 31;
            float fsum, inv_cnt;
            if (w == 0) {
                fsum = cf[s * 64 + lane] + cf[s * 64 + 32 + lane];
                inv_cnt = 1.0f / 64.0f;
            } else if (w == 7) {
                fsum = cl[s * 64 + lane] + cl[s * 64 + 32 + lane];
                inv_cnt = 1.0f / 64.0f;
            } else {
                const float* base = smem + (w - 1) * 2048;
                fsum = 0.f;
#pragma unroll
                for (int i = 0; i < 64; ++i) fsum += base[i * 32 + lane];
                inv_cnt = 1.0f / 2048.0f;
            }
#pragma unroll
            for (int o = 16; o; o >>= 1) fsum += __shfl_xor_sync(0xffffffffu, fsum, o);
            if (lane == 0) g_feats[s * NQ + w] = fsum * inv_cnt;
        }
    }
    gbar();

    // ===== P3: slot overlaps (blocks 16..79; cm still in smem) =====
    if (blk >= 16) {
        const int s = blk - 16;
        if (tid < 256) {
            const int w = tid >> 5;
            const int lane = tid & 31;
            const int b = w;   // batch = warp
            float M0[NQ], M1[NQ];
#pragma unroll
            for (int q = 0; q < NQ; ++q) {
                M0[q] = __ldcg(&g_m0[b * 32 + q]);
                M1[q] = __ldcg(&g_m1[b * 32 + q]);
            }
            float v = M0[0] * cf[s * 64 + lane] + M1[0] * cf[s * 64 + 32 + lane];
#pragma unroll
            for (int q = 1; q <= NQ - 2; ++q) {
                const float* base = smem + (q - 1) * 2048;
                float nv = 0.f;
#pragma unroll 8
                for (int l = 0; l < BOND; ++l) {
                    float vl = __shfl_sync(0xffffffffu, v, l);
                    float c0 = base[l * 64 + lane];
                    float c1 = base[l * 64 + 32 + lane];
                    nv = fmaf(vl, fmaf(M0[q], c0, M1[q] * c1), nv);
                }
                v = nv;
            }
            float wl = M0[NQ - 1] * cl[(s * BOND + lane) * 2] +
                       M1[NQ - 1] * cl[(s * BOND + lane) * 2 + 1];
            float ov = v * wl;
#pragma unroll
            for (int o = 16; o; o >>= 1) ov += __shfl_xor_sync(0xffffffffu, ov, o);
            if (lane == 0) g_overlaps[b * S + s] = ov;
        }
    }
    gbar();

    // ===== P4: blocks 0..7 — attention + gg for batch b, write bias row =====
    if (blk < B) {
        const int b = blk;
        float* s_gg = smem;   // 8

        if (tid < 32) {
            const int lane = tid;
            float a0 = __ldcg(&g_overlaps[b * S + lane]);
            float a1 = __ldcg(&g_overlaps[b * S + 32 + lane]);
            float m = fmaxf(a0, a1);
#pragma unroll
            for (int o = 16; o; o >>= 1) m = fmaxf(m, __shfl_xor_sync(0xffffffffu, m, o));
            float e0 = __expf(a0 - m);
            float e1 = __expf(a1 - m);
            float ssum = e0 + e1;
#pragma unroll
            for (int o = 16; o; o >>= 1) ssum += __shfl_xor_sync(0xffffffffu, ssum, o);
            const float inv = 1.0f / ssum;
            const float at0 = e0 * inv;
            const float at1 = e1 * inv;
#pragma unroll
            for (int q = 0; q < NQ; ++q) {
                float p = at0 * __ldcg(&g_feats[lane * NQ + q]) +
                          at1 * __ldcg(&g_feats[(32 + lane) * NQ + q]);
#pragma unroll
                for (int o = 16; o; o >>= 1) p += __shfl_xor_sync(0xffffffffu, p, o);
                if (lane == 0) s_gg[q] = p;
            }
        }
        __syncthreads();

        float acc = bd[tid];
#pragma unroll
        for (int q = 0; q < NQ; ++q)
            acc = fmaf(s_gg[q], __ldcg(&g_fold[q * D + tid]), acc);
        g_bias[b * D + tid] = acc;
    }
}

// ============ Kernel 3: out = x + bias (proven config: 8192 x 256) ============
__global__ void k_add(const float* __restrict__ x, float* __restrict__ out) {
    const int blk = blockIdx.x;
    const int b = blk >> 10;               // 1024 blocks per batch
    const size_t row0 = (size_t)blk * 4;
    const int tid = threadIdx.x;
    const float4 bias = reinterpret_cast<const float4*>(g_bias)[b * (D / 4) + tid];
    const float4* xp = reinterpret_cast<const float4*>(x) + row0 * (D / 4);
    float4* op = reinterpret_cast<float4*>(out) + row0 * (D / 4);
#pragma unroll
    for (int r = 0; r < 4; ++r) {
        float4 v = xp[r * (D / 4) + tid];
        v.x += bias.x; v.y += bias.y; v.z += bias.z; v.w += bias.w;
        op[r * (D / 4) + tid] = v;
    }
}

extern "C" void kernel_launch(void* const* d_in, const int* in_sizes, int n_in,
                              void* d_out, int out_size) {
    const float* x  = (const float*)d_in[0];
    const float* Wq = (const float*)d_in[1];
    const float* bq = (const float*)d_in[2];
    const float* Wd = (const float*)d_in[3];
    const float* bd = (const float*)d_in[4];
    const float* cf = (const float*)d_in[5];
    const float* cm = (const float*)d_in[6];
    const float* cl = (const float*)d_in[7];
    float* out = (float*)d_out;

    k_partsum<<<dim3(NCH, B), 256>>>(x);
    k_mid<<<NMID, NT>>>(Wq, bq, Wd, bd, cf, cm, cl);
    k_add<<<(B * T) / 4, 256>>>(x, out);
}

// round 16
// speedup vs baseline: 1.6700x; 1.0208x over previous
#include <cuda_runtime.h>
#include <cstdint>

#define B 8
#define T 4096
#define D 1024
#define S 64
#define BOND 32
#define NQ 8
#define QDIM 256
#define NCH 64         // chunks per batch (64 rows each)
#define NMID 80        // k_mid blocks (co-resident, gbar-safe)
#define NT 1024

// ------- device scratch (no allocations allowed) -------
__device__ float g_part[B * NCH * D];    // per-chunk column sums (2 MB)
__device__ float g_lp[64 * B * QDIM];    // per-kslice logit partials (512 KB)
__device__ float g_m0[B * 32];           // padded per batch
__device__ float g_m1[B * 32];
__device__ float g_overlaps[B * S];
__device__ float g_feats[S * NQ];
__device__ float g_fold[NQ * D];         // folded Wd
__device__ float g_bias[B * D];          // final per-batch bias rows
__device__ int   g_bar_count;            // zero-init
__device__ int   g_bar_gen;

// ---------------- software grid barrier (NMID blocks, all co-resident) ----------------
__device__ __forceinline__ void gbar() {
    __threadfence();
    __syncthreads();
    if (threadIdx.x == 0) {
        int gen = *(volatile int*)&g_bar_gen;
        if (atomicAdd(&g_bar_count, 1) == NMID - 1) {
            *(volatile int*)&g_bar_count = 0;
            __threadfence();
            *(volatile int*)&g_bar_gen = gen + 1;
        } else {
            while (*(volatile int*)&g_bar_gen == gen) __nanosleep(64);
        }
    }
    __syncthreads();
}

// ==== Kernel 1: per-chunk column sums (blocks 0..511) | fold Wd (blocks 512..543) ====
__global__ void k_partsum(const float* __restrict__ x, const float* __restrict__ Wd) {
    const int blk = blockIdx.x;
    const int tid = threadIdx.x;
    if (blk < 512) {
        const int c = blk & 63;
        const int b = blk >> 6;
        const float4* xp = reinterpret_cast<const float4*>(x) +
                           ((size_t)b * T + (size_t)c * 64) * 256 + tid;
        float4 acc = make_float4(0.f, 0.f, 0.f, 0.f);
#pragma unroll 8
        for (int r = 0; r < 64; ++r) {
            float4 v = xp[(size_t)r * 256];
            acc.x += v.x; acc.y += v.y; acc.z += v.z; acc.w += v.w;
        }
        reinterpret_cast<float4*>(g_part)[((size_t)b * NCH + c) * 256 + tid] = acc;
    } else {
        // fold[q][d] = sum_i Wd[i*8+q][d]; 32 blocks x 32 d's (overlaps with x stream)
        const int d = (blk - 512) * 32 + (tid >> 3);
        const int q = tid & 7;
        float acc = 0.f;
#pragma unroll 8
        for (int i = 0; i < 32; ++i)
            acc += Wd[(size_t)(i * 8 + q) * D + d];
        g_fold[q * D + d] = acc;
    }
}

// ============ Kernel 2: middle work, 80 x 1024, 3 gbars ============
__global__ void __launch_bounds__(NT, 1)
k_mid(const float* __restrict__ Wq,
      const float* __restrict__ bq,
      const float* __restrict__ bd,
      const float* __restrict__ cf,
      const float* __restrict__ cm,
      const float* __restrict__ cl) {
    __shared__ float smem[12288];   // 48 KB
    const int blk = blockIdx.x;
    const int tid = threadIdx.x;

    // ===== P1: GEMV partials for ALL batches (blocks 0..63) =====
    if (blk < 64) {
        float* pr = smem;            // 4 x 8 x 256 = 8192 floats (32 KB)
        float* xs_s = smem + 8192;   // 8 x 16 = 128 floats
        const int k0 = blk * 16;

        // self-gather xs slice: pair = (b, k'), 8 sub-threads each sum 8 c's
        {
            const int pair = tid >> 3;         // 0..127
            const int sub = tid & 7;
            const int b = pair >> 4;
            const int kk = pair & 15;
            float acc = 0.f;
#pragma unroll
            for (int m = 0; m < 8; ++m)
                acc += g_part[((size_t)b * NCH + (sub + 8 * m)) * D + k0 + kk];
#pragma unroll
            for (int o = 4; o; o >>= 1) acc += __shfl_xor_sync(0xffffffffu, acc, o);
            if (sub == 0) xs_s[b * 16 + kk] = acc * (1.0f / (float)T);
        }
        __syncthreads();

        // partial GEMV: thread (j, kc) covers 4 k's for all 8 batches
        const int j = tid & 255;
        const int kc = tid >> 8;
        {
            float acc[B];
#pragma unroll
            for (int b = 0; b < B; ++b) acc[b] = 0.f;
#pragma unroll
            for (int i = 0; i < 4; ++i) {
                const int kk = kc * 4 + i;
                const float wq = Wq[(size_t)(k0 + kk) * QDIM + j];
#pragma unroll
                for (int b = 0; b < B; ++b)
                    acc[b] = fmaf(xs_s[b * 16 + kk], wq, acc[b]);
            }
#pragma unroll
            for (int b = 0; b < B; ++b)
                pr[(kc * 8 + b) * 256 + j] = acc[b];
        }
        __syncthreads();

        // reduce over kc, store g_lp[blk][b][j]
#pragma unroll
        for (int h = 0; h < 2; ++h) {
            const int idx = tid + h * 1024;    // (b, j)
            const int b = idx >> 8;
            const int jj = idx & 255;
            float v = pr[(0 * 8 + b) * 256 + jj] + pr[(1 * 8 + b) * 256 + jj] +
                      pr[(2 * 8 + b) * 256 + jj] + pr[(3 * 8 + b) * 256 + jj];
            g_lp[((size_t)blk * B + b) * QDIM + jj] = v;
        }
    }
    gbar();

    // ===== P2: query finish (blocks 0..7) | cm preload + feats (blocks 16..79) =====
    if (blk < B) {
        float* pr2 = smem;           // 4 x 256
        float* qa = smem + 1024;     // 256
        float* red = smem + 1280;    // 8
        const int b = blk;
        const int j = tid & 255;
        const int pc = tid >> 8;
        {
            float acc = 0.f;
#pragma unroll
            for (int i = 0; i < 16; ++i) {
                const int p = pc * 16 + i;
                acc += g_lp[((size_t)p * B + b) * QDIM + j];
            }
            pr2[pc * 256 + j] = acc;
        }
        __syncthreads();

        float logit = 0.f;
        if (tid < QDIM)
            logit = (pr2[j] + pr2[256 + j]) + (pr2[512 + j] + pr2[768 + j]) + bq[j];

        // softmax over 256 — barriers uniform
        float m = logit;
#pragma unroll
        for (int o = 16; o; o >>= 1) m = fmaxf(m, __shfl_xor_sync(0xffffffffu, m, o));
        if (tid < QDIM && (tid & 31) == 0) red[tid >> 5] = m;
        __syncthreads();
        float bm = red[0];
#pragma unroll
        for (int i = 1; i < 8; ++i) bm = fmaxf(bm, red[i]);
        float e = (tid < QDIM) ? __expf(logit - bm) : 0.f;
        float ssum = e;
#pragma unroll
        for (int o = 16; o; o >>= 1) ssum += __shfl_xor_sync(0xffffffffu, ssum, o);
        __syncthreads();
        if (tid < QDIM && (tid & 31) == 0) red[tid >> 5] = ssum;
        __syncthreads();
        float tot = 0.f;
#pragma unroll
        for (int i = 0; i < 8; ++i) tot += red[i];
        if (tid < QDIM) qa[j] = e / tot;
        __syncthreads();

        if (tid < 16) {   // amplitude means, JAX OOB-clamp to index 255
            const int q = tid & 7;
            const bool one = tid >= 8;
            const int s = 1 << (7 - q);
            const int cin = min(s, 128 / s);
            float a = 0.f;
            const int off = one ? s : 0;
            for (int i = 0; i < cin; ++i) a += qa[i * 2 * s + off];
            a += (float)(s - cin) * qa[QDIM - 1];
            float* dst = one ? g_m1 : g_m0;
            dst[b * 32 + q] = a / (float)s;
        }
    } else if (blk >= 16) {
        // preload this slot's cm slice into smem + compute feats (query-independent)
        const int s = blk - 16;
        {
            const float4* src = reinterpret_cast<const float4*>(cm + (size_t)s * 12288);
            float4* dst = reinterpret_cast<float4*>(smem);
#pragma unroll
            for (int i = 0; i < 3; ++i)
                dst[i * 1024 + tid] = src[i * 1024 + tid];
        }
        __syncthreads();

        if (tid < 256) {
            const int w = tid >> 5;
            const int lane = tid & 31;
            float fsum, inv_cnt;
            if (w == 0) {
                fsum = cf[s * 64 + lane] + cf[s * 64 + 32 + lane];
                inv_cnt = 1.0f / 64.0f;
            } else if (w == 7) {
                fsum = cl[s * 64 + lane] + cl[s * 64 + 32 + lane];
                inv_cnt = 1.0f / 64.0f;
            } else {
                const float* base = smem + (w - 1) * 2048;
                fsum = 0.f;
#pragma unroll
                for (int i = 0; i < 64; ++i) fsum += base[i * 32 + lane];
                inv_cnt = 1.0f / 2048.0f;
            }
#pragma unroll
            for (int o = 16; o; o >>= 1) fsum += __shfl_xor_sync(0xffffffffu, fsum, o);
            if (lane == 0) g_feats[s * NQ + w] = fsum * inv_cnt;
        }
    }
    gbar();

    // ===== P3: slot overlaps (blocks 16..79; cm still in smem) =====
    if (blk >= 16) {
        const int s = blk - 16;
        if (tid < 256) {
            const int w = tid >> 5;
            const int lane = tid & 31;
            const int b = w;   // batch = warp
            float M0[NQ], M1[NQ];
#pragma unroll
            for (int q = 0; q < NQ; ++q) {
                M0[q] = __ldcg(&g_m0[b * 32 + q]);
                M1[q] = __ldcg(&g_m1[b * 32 + q]);
            }
            float v = M0[0] * cf[s * 64 + lane] + M1[0] * cf[s * 64 + 32 + lane];
#pragma unroll
            for (int q = 1; q <= NQ - 2; ++q) {
                const float* base = smem + (q - 1) * 2048;
                float nv = 0.f;
#pragma unroll 8
                for (int l = 0; l < BOND; ++l) {
                    float vl = __shfl_sync(0xffffffffu, v, l);
                    float c0 = base[l * 64 + lane];
                    float c1 = base[l * 64 + 32 + lane];
                    nv = fmaf(vl, fmaf(M0[q], c0, M1[q] * c1), nv);
                }
                v = nv;
            }
            float wl = M0[NQ - 1] * cl[(s * BOND + lane) * 2] +
                       M1[NQ - 1] * cl[(s * BOND + lane) * 2 + 1];
            float ov = v * wl;
#pragma unroll
            for (int o = 16; o; o >>= 1) ov += __shfl_xor_sync(0xffffffffu, ov, o);
            if (lane == 0) g_overlaps[b * S + s] = ov;
        }
    }
    gbar();

    // ===== P4: blocks 0..7 — attention + gg for batch b, write bias row =====
    if (blk < B) {
        const int b = blk;
        float* s_gg = smem;   // 8

        if (tid < 32) {
            const int lane = tid;
            float a0 = __ldcg(&g_overlaps[b * S + lane]);
            float a1 = __ldcg(&g_overlaps[b * S + 32 + lane]);
            float m = fmaxf(a0, a1);
#pragma unroll
            for (int o = 16; o; o >>= 1) m = fmaxf(m, __shfl_xor_sync(0xffffffffu, m, o));
            float e0 = __expf(a0 - m);
            float e1 = __expf(a1 - m);
            float ssum = e0 + e1;
#pragma unroll
            for (int o = 16; o; o >>= 1) ssum += __shfl_xor_sync(0xffffffffu, ssum, o);
            const float inv = 1.0f / ssum;
            const float at0 = e0 * inv;
            const float at1 = e1 * inv;
#pragma unroll
            for (int q = 0; q < NQ; ++q) {
                float p = at0 * __ldcg(&g_feats[lane * NQ + q]) +
                          at1 * __ldcg(&g_feats[(32 + lane) * NQ + q]);
#pragma unroll
                for (int o = 16; o; o >>= 1) p += __shfl_xor_sync(0xffffffffu, p, o);
                if (lane == 0) s_gg[q] = p;
            }
        }
        __syncthreads();

        float acc = bd[tid];
#pragma unroll
        for (int q = 0; q < NQ; ++q)
            acc = fmaf(s_gg[q], __ldcg(&g_fold[q * D + tid]), acc);
        g_bias[b * D + tid] = acc;
    }
}

// ==== Kernel 3: out = x + bias — REVERSED block order (x tail is L2-hot) ====
__global__ void k_add(const float* __restrict__ x, float* __restrict__ out) {
    const int rblk = (int)(gridDim.x - 1) - (int)blockIdx.x;   // reversed
    const int b = rblk >> 10;               // 1024 blocks per batch
    const size_t row0 = (size_t)rblk * 4;
    const int tid = threadIdx.x;
    const float4 bias = reinterpret_cast<const float4*>(g_bias)[b * (D / 4) + tid];
    const float4* xp = reinterpret_cast<const float4*>(x) + row0 * (D / 4);
    float4* op = reinterpret_cast<float4*>(out) + row0 * (D / 4);
#pragma unroll
    for (int r = 0; r < 4; ++r) {
        float4 v = xp[r * (D / 4) + tid];
        v.x += bias.x; v.y += bias.y; v.z += bias.z; v.w += bias.w;
        op[r * (D / 4) + tid] = v;
    }
}

extern "C" void kernel_launch(void* const* d_in, const int* in_sizes, int n_in,
                              void* d_out, int out_size) {
    const float* x  = (const float*)d_in[0];
    const float* Wq = (const float*)d_in[1];
    const float* bq = (const float*)d_in[2];
    const float* Wd = (const float*)d_in[3];
    const float* bd = (const float*)d_in[4];
    const float* cf = (const float*)d_in[5];
    const float* cm = (const float*)d_in[6];
    const float* cl = (const float*)d_in[7];
    float* out = (float*)d_out;

    k_partsum<<<544, 256>>>(x, Wd);
    k_mid<<<NMID, NT>>>(Wq, bq, bd, cf, cm, cl);
    k_add<<<(B * T) / 4, 256>>>(x, out);
}